// round 2
// baseline (speedup 1.0000x reference)
#include <cuda_runtime.h>

#define DIMC 512
#define NPOS 256
#define NB   2
#define NTAB 961
#define QKV_STRIDE (3 * DIMC * NPOS)
#define LOG2E 1.4426950408889634f
#define SCALE 0.044194173824159216f   // 512^-0.5
#define DBLK 8

// Scratch (device globals: no allocations allowed)
__device__ float g_qkv [NB * 3 * DIMC * NPOS];  // [b][o][p]
__device__ float g_o   [NB * DIMC * NPOS];      // [b][d][h]
__device__ float g_bias[NPOS * NPOS];           // biasT[g][h] * log2e

// ---------------------------------------------------------------------------
// C[m][n] = sum_k A[m][k]*B[k][n] + bias[m].  64x64 tile, 256 thr, 4x4/thread.
// M,N multiples of 64; K multiple of 16. B,C have per-batch (blockIdx.z) strides.
// ---------------------------------------------------------------------------
__global__ __launch_bounds__(256) void gemm64(
        const float* __restrict__ A,
        const float* __restrict__ Bm, long sB,
        const float* __restrict__ bias,
        float* __restrict__ C, long sC,
        int M, int N, int K) {
    const float* Bp = Bm + (long)blockIdx.z * sB;
    float*       Cp = C  + (long)blockIdx.z * sC;

    __shared__ float As[16][68];   // [k][m], padded
    __shared__ float Bs[16][64];   // [k][n]

    const int tid = threadIdx.x;
    const int tx = tid & 15, ty = tid >> 4;
    const int m0 = blockIdx.y * 64, n0 = blockIdx.x * 64;

    // load indices
    const int la_m = tid >> 2;            // 0..63
    const int la_k = (tid & 3) * 4;       // 0,4,8,12
    const int lb_k = tid >> 4;            // 0..15
    const int lb_n = (tid & 15) * 4;      // 0..60

    float acc[4][4];
#pragma unroll
    for (int i = 0; i < 4; i++)
#pragma unroll
        for (int j = 0; j < 4; j++) acc[i][j] = 0.f;

    for (int kt = 0; kt < K; kt += 16) {
        float4 av = *(const float4*)&A [(long)(m0 + la_m) * K + kt + la_k];
        float4 bv = *(const float4*)&Bp[(long)(kt + lb_k) * N + n0 + lb_n];
        As[la_k + 0][la_m] = av.x;
        As[la_k + 1][la_m] = av.y;
        As[la_k + 2][la_m] = av.z;
        As[la_k + 3][la_m] = av.w;
        *(float4*)&Bs[lb_k][lb_n] = bv;
        __syncthreads();
#pragma unroll
        for (int kk = 0; kk < 16; kk++) {
            float4 a4 = *(const float4*)&As[kk][ty * 4];
            float4 b4 = *(const float4*)&Bs[kk][tx * 4];
            float ar[4] = {a4.x, a4.y, a4.z, a4.w};
            float br[4] = {b4.x, b4.y, b4.z, b4.w};
#pragma unroll
            for (int i = 0; i < 4; i++)
#pragma unroll
                for (int j = 0; j < 4; j++)
                    acc[i][j] = fmaf(ar[i], br[j], acc[i][j]);
        }
        __syncthreads();
    }

#pragma unroll
    for (int i = 0; i < 4; i++) {
        int m = m0 + ty * 4 + i;
        float bb = bias ? bias[m] : 0.f;
        float4 o;
        o.x = acc[i][0] + bb; o.y = acc[i][1] + bb;
        o.z = acc[i][2] + bb; o.w = acc[i][3] + bb;
        *(float4*)&Cp[(long)m * N + n0 + tx * 4] = o;
    }
}

// ---------------------------------------------------------------------------
// biasT[g*256+h] = rpb[mod((h/16-g/16)+(h%16-g%16), 961)] * log2e
// ---------------------------------------------------------------------------
__global__ void make_bias(const float* __restrict__ rpb) {
    int idx = blockIdx.x * 256 + threadIdx.x;
    int g = idx >> 8, h = idx & 255;
    int v = ((h >> 4) - (g >> 4)) + ((h & 15) - (g & 15));   // [-30,30]
    g_bias[idx] = rpb[(v + NTAB) % NTAB] * LOG2E;
}

// ---------------------------------------------------------------------------
// Per-channel attention. CTA = (d-block of 8, b). Thread h handles row h for
// all 8 channels. out[d][h] = sum_g exp2(a'[d]*k[d][g] + biasT[g][h]) * v[d][g]
//                            / sum_g exp2(...)
// ---------------------------------------------------------------------------
__global__ __launch_bounds__(256) void chan_attn() {
    const int b  = blockIdx.y;
    const int d0 = blockIdx.x * DBLK;
    const int h  = threadIdx.x;

    const float* base = g_qkv + (long)b * QKV_STRIDE;
    __shared__ float2 skv[DBLK][NPOS];

    float a[DBLK], num[DBLK], den[DBLK];
#pragma unroll
    for (int d = 0; d < DBLK; d++) {
        float kk = base[(long)(DIMC   + d0 + d) * NPOS + h];
        float vv = base[(long)(2*DIMC + d0 + d) * NPOS + h];
        skv[d][h] = make_float2(kk, vv);
        a[d]   = base[(long)(d0 + d) * NPOS + h] * (SCALE * LOG2E);
        num[d] = 0.f;
        den[d] = 0.f;
    }
    __syncthreads();

#pragma unroll 4
    for (int g = 0; g < NPOS; g++) {
        float bb = g_bias[g * NPOS + h];
#pragma unroll
        for (int d = 0; d < DBLK; d++) {
            float2 kv = skv[d][g];
            float e = exp2f(fmaf(a[d], kv.x, bb));
            num[d] = fmaf(e, kv.y, num[d]);
            den[d] += e;
        }
    }

#pragma unroll
    for (int d = 0; d < DBLK; d++)
        g_o[((long)b * DIMC + d0 + d) * NPOS + h] = num[d] / den[d];
}

// ---------------------------------------------------------------------------
extern "C" void kernel_launch(void* const* d_in, const int* in_sizes, int n_in,
                              void* d_out, int out_size) {
    const float* x      = (const float*)d_in[0];  // (2,512,256,1)
    const float* qkv_w  = (const float*)d_in[1];  // (1536,512)
    const float* qkv_b  = (const float*)d_in[2];  // (1536)
    const float* proj_w = (const float*)d_in[3];  // (512,512)
    const float* proj_b = (const float*)d_in[4];  // (512)
    const float* rpb    = (const float*)d_in[5];  // (961,1)
    float* out = (float*)d_out;                   // (2,512,256,1)

    float *qkv_ptr, *o_ptr;
    cudaGetSymbolAddress((void**)&qkv_ptr, g_qkv);
    cudaGetSymbolAddress((void**)&o_ptr,   g_o);

    // bias table (independent of GEMM)
    make_bias<<<NPOS * NPOS / 256, 256>>>(rpb);

    // QKV: [1536 x 256] = qkv_w[1536 x 512] * x_b[512 x 256] + qkv_b
    {
        dim3 grid(NPOS / 64, (3 * DIMC) / 64, NB);
        gemm64<<<grid, 256>>>(qkv_w, x, (long)DIMC * NPOS, qkv_b,
                              qkv_ptr, (long)QKV_STRIDE,
                              3 * DIMC, NPOS, DIMC);
    }

    // per-channel attention
    {
        dim3 grid(DIMC / DBLK, NB);
        chan_attn<<<grid, 256>>>();
    }

    // out = proj_w[512 x 512] * O[512 x 256] + proj_b
    {
        dim3 grid(NPOS / 64, DIMC / 64, NB);
        gemm64<<<grid, 256>>>(proj_w, o_ptr, (long)DIMC * NPOS, proj_b,
                              out, (long)DIMC * NPOS,
                              DIMC, NPOS, DIMC);
    }
}

// round 3
// speedup vs baseline: 1.0064x; 1.0064x over previous
#include <cuda_runtime.h>

#define DIMC 512
#define NPOS 256
#define NB   2
#define NTAB 961
#define QKV_STRIDE (3 * DIMC * NPOS)
#define LOG2E 1.4426950408889634f
#define SCALE 0.044194173824159216f   // 512^-0.5
#define DBLK 8
#define PSPLIT 4                       // split-K factor for proj

// Scratch (device globals: no allocations allowed)
__device__ float g_qkv [NB * 3 * DIMC * NPOS];     // [b][o][p]
__device__ float g_o   [NB * DIMC * NPOS];         // [b][d][h]
__device__ float g_bias[NPOS * NPOS];              // biasT[g][h] * log2e
__device__ float g_part[NB * PSPLIT * DIMC * NPOS];// proj split-K partials

// ---------------------------------------------------------------------------
// C[m][n] = sum_k A[m][k]*B[k][n] (+ bias[m]).  64x64 CTA tile, 64 threads,
// 8x8 register tile / thread, double-buffered smem, KB=16.
// SPLIT>1: blockIdx.z = b*SPLIT + ks; each part sums K/SPLIT and writes its
// own slab of C (stride sC per z). SPLIT==1: z = batch.
// ---------------------------------------------------------------------------
template<int SPLIT, bool HAS_BIAS>
__global__ __launch_bounds__(64) void gemm_ff(
        const float* __restrict__ A,
        const float* __restrict__ Bm, long sB,
        const float* __restrict__ bias,
        float* __restrict__ C, long sC,
        int M, int N, int K) {
    const int z  = blockIdx.z;
    const int b  = z / SPLIT;
    const int ks = z % SPLIT;
    const int kchunk = K / SPLIT;
    const int kbeg = ks * kchunk, kend = kbeg + kchunk;

    const float* Bp = Bm + (long)b * sB;
    float*       Cp = C  + (long)z * sC;

    __shared__ float As[2][16][68];   // [buf][k][m]
    __shared__ float Bs[2][16][64];   // [buf][k][n]

    const int t  = threadIdx.x;
    const int tx = t & 7, ty = t >> 3;
    const int m0 = blockIdx.y * 64, n0 = blockIdx.x * 64;

    const float* aRow = A  + (long)(m0 + t) * K;
    const float* bRow = Bp + (long)(t >> 2) * N + n0 + (t & 3) * 16;

    float4 ra[4], rb[4];
    float acc[8][8];
#pragma unroll
    for (int i = 0; i < 8; i++)
#pragma unroll
        for (int j = 0; j < 8; j++) acc[i][j] = 0.f;

    // prologue: load & stage first k-block
#pragma unroll
    for (int j = 0; j < 4; j++) ra[j] = *(const float4*)(aRow + kbeg + 4 * j);
#pragma unroll
    for (int j = 0; j < 4; j++) rb[j] = *(const float4*)(bRow + (long)kbeg * N + 4 * j);
#pragma unroll
    for (int j = 0; j < 4; j++) {
        As[0][4*j+0][t] = ra[j].x; As[0][4*j+1][t] = ra[j].y;
        As[0][4*j+2][t] = ra[j].z; As[0][4*j+3][t] = ra[j].w;
        *(float4*)&Bs[0][t >> 2][(t & 3) * 16 + 4 * j] = rb[j];
    }
    __syncthreads();

    int p = 0;
    for (int kt = kbeg; kt < kend; kt += 16) {
        const bool more = (kt + 16 < kend);
        if (more) {
#pragma unroll
            for (int j = 0; j < 4; j++) ra[j] = *(const float4*)(aRow + kt + 16 + 4 * j);
#pragma unroll
            for (int j = 0; j < 4; j++) rb[j] = *(const float4*)(bRow + (long)(kt + 16) * N + 4 * j);
        }
#pragma unroll
        for (int kk = 0; kk < 16; kk++) {
            float4 a0 = *(const float4*)&As[p][kk][ty * 8];
            float4 a1 = *(const float4*)&As[p][kk][ty * 8 + 4];
            float4 b0 = *(const float4*)&Bs[p][kk][tx * 8];
            float4 b1 = *(const float4*)&Bs[p][kk][tx * 8 + 4];
            float ar[8] = {a0.x,a0.y,a0.z,a0.w,a1.x,a1.y,a1.z,a1.w};
            float br[8] = {b0.x,b0.y,b0.z,b0.w,b1.x,b1.y,b1.z,b1.w};
#pragma unroll
            for (int i = 0; i < 8; i++)
#pragma unroll
                for (int j = 0; j < 8; j++)
                    acc[i][j] = fmaf(ar[i], br[j], acc[i][j]);
        }
        if (more) {
#pragma unroll
            for (int j = 0; j < 4; j++) {
                As[p^1][4*j+0][t] = ra[j].x; As[p^1][4*j+1][t] = ra[j].y;
                As[p^1][4*j+2][t] = ra[j].z; As[p^1][4*j+3][t] = ra[j].w;
                *(float4*)&Bs[p^1][t >> 2][(t & 3) * 16 + 4 * j] = rb[j];
            }
            __syncthreads();
            p ^= 1;
        }
    }

#pragma unroll
    for (int i = 0; i < 8; i++) {
        int m = m0 + ty * 8 + i;
        float bb = HAS_BIAS ? bias[m] : 0.f;
        float4 o0, o1;
        o0.x = acc[i][0] + bb; o0.y = acc[i][1] + bb;
        o0.z = acc[i][2] + bb; o0.w = acc[i][3] + bb;
        o1.x = acc[i][4] + bb; o1.y = acc[i][5] + bb;
        o1.z = acc[i][6] + bb; o1.w = acc[i][7] + bb;
        *(float4*)&Cp[(long)m * N + n0 + tx * 8]     = o0;
        *(float4*)&Cp[(long)m * N + n0 + tx * 8 + 4] = o1;
    }
}

// ---------------------------------------------------------------------------
// Deterministic split-K reduction for proj: out = sum_ks part + bias[m]
// ---------------------------------------------------------------------------
__global__ __launch_bounds__(256) void proj_reduce(const float* __restrict__ bias,
                                                   float* __restrict__ out) {
    const int v4 = blockIdx.x * 256 + threadIdx.x;      // float4 index
    const long MN = (long)DIMC * NPOS;
    const long idx = (long)v4 * 4;                      // within NB*MN
    const int b  = (int)(idx / MN);
    const long mn = idx - (long)b * MN;
    const int m  = (int)(mn / NPOS);

    const float* p0 = g_part + ((long)b * PSPLIT) * MN + mn;
    float4 s = *(const float4*)p0;
#pragma unroll
    for (int ks = 1; ks < PSPLIT; ks++) {
        float4 q = *(const float4*)(p0 + (long)ks * MN);
        s.x += q.x; s.y += q.y; s.z += q.z; s.w += q.w;
    }
    float bb = bias[m];
    s.x += bb; s.y += bb; s.z += bb; s.w += bb;
    *(float4*)(out + idx) = s;
}

// ---------------------------------------------------------------------------
// biasT[g*256+h] = rpb[mod((h/16-g/16)+(h%16-g%16), 961)] * log2e
// ---------------------------------------------------------------------------
__global__ void make_bias(const float* __restrict__ rpb) {
    int idx = blockIdx.x * 256 + threadIdx.x;
    int g = idx >> 8, h = idx & 255;
    int v = ((h >> 4) - (g >> 4)) + ((h & 15) - (g & 15));
    g_bias[idx] = rpb[(v + NTAB) % NTAB] * LOG2E;
}

// ---------------------------------------------------------------------------
// Per-channel attention. CTA = (d-block of 8, b). Thread h handles row h.
// ---------------------------------------------------------------------------
__global__ __launch_bounds__(256) void chan_attn() {
    const int b  = blockIdx.y;
    const int d0 = blockIdx.x * DBLK;
    const int h  = threadIdx.x;

    const float* base = g_qkv + (long)b * QKV_STRIDE;
    __shared__ float2 skv[DBLK][NPOS];

    float a[DBLK], num[DBLK], den[DBLK];
#pragma unroll
    for (int d = 0; d < DBLK; d++) {
        float kk = base[(long)(DIMC   + d0 + d) * NPOS + h];
        float vv = base[(long)(2*DIMC + d0 + d) * NPOS + h];
        skv[d][h] = make_float2(kk, vv);
        a[d]   = base[(long)(d0 + d) * NPOS + h] * (SCALE * LOG2E);
        num[d] = 0.f;
        den[d] = 0.f;
    }
    __syncthreads();

    const float* bp = g_bias + h;
#pragma unroll 4
    for (int g = 0; g < NPOS; g++) {
        float bb = __ldg(bp + g * NPOS);
#pragma unroll
        for (int d = 0; d < DBLK; d++) {
            float2 kv = skv[d][g];
            float e = exp2f(fmaf(a[d], kv.x, bb));
            num[d] = fmaf(e, kv.y, num[d]);
            den[d] += e;
        }
    }

#pragma unroll
    for (int d = 0; d < DBLK; d++)
        g_o[((long)b * DIMC + d0 + d) * NPOS + h] = num[d] / den[d];
}

// ---------------------------------------------------------------------------
extern "C" void kernel_launch(void* const* d_in, const int* in_sizes, int n_in,
                              void* d_out, int out_size) {
    const float* x      = (const float*)d_in[0];  // (2,512,256,1)
    const float* qkv_w  = (const float*)d_in[1];  // (1536,512)
    const float* qkv_b  = (const float*)d_in[2];  // (1536)
    const float* proj_w = (const float*)d_in[3];  // (512,512)
    const float* proj_b = (const float*)d_in[4];  // (512)
    const float* rpb    = (const float*)d_in[5];  // (961,1)
    float* out = (float*)d_out;                   // (2,512,256,1)

    float *qkv_ptr, *o_ptr, *part_ptr;
    cudaGetSymbolAddress((void**)&qkv_ptr, g_qkv);
    cudaGetSymbolAddress((void**)&o_ptr,   g_o);
    cudaGetSymbolAddress((void**)&part_ptr, g_part);

    // bias table (independent of GEMM)
    make_bias<<<NPOS * NPOS / 256, 256>>>(rpb);

    // QKV: [1536 x 256] = qkv_w * x_b + qkv_b   (192 CTAs)
    {
        dim3 grid(NPOS / 64, (3 * DIMC) / 64, NB);
        gemm_ff<1, true><<<grid, 64>>>(qkv_w, x, (long)DIMC * NPOS, qkv_b,
                                       qkv_ptr, (long)QKV_STRIDE,
                                       3 * DIMC, NPOS, DIMC);
    }

    // per-channel attention (128 CTAs)
    {
        dim3 grid(DIMC / DBLK, NB);
        chan_attn<<<grid, 256>>>();
    }

    // proj split-K: partials (256 CTAs), then deterministic reduce
    {
        dim3 grid(NPOS / 64, DIMC / 64, NB * PSPLIT);
        gemm_ff<PSPLIT, false><<<grid, 64>>>(proj_w, o_ptr, (long)DIMC * NPOS,
                                             nullptr,
                                             part_ptr, (long)DIMC * NPOS,
                                             DIMC, NPOS, DIMC);
        proj_reduce<<<(NB * DIMC * NPOS / 4) / 256, 256>>>(proj_b, out);
    }
}

// round 6
// speedup vs baseline: 1.4679x; 1.4585x over previous
#include <cuda_runtime.h>
#include <cuda_bf16.h>
#include <cstdint>

#define DIMC  512
#define NPOS  256
#define NB    2
#define NTAB  961
#define KDIM  512
#define KC    64                 // bf16 k per chunk = 128 bytes = SW128 row
#define NCHUNK (KDIM / KC)
#define LOG2E 1.4426950408889634f
#define SCALE 0.044194173824159216f   // 512^-0.5
#define DBLK  8

// ---------------- scratch (device globals; no allocs) ----------------
__device__ float g_qkv [NB * 3 * DIMC * NPOS];                 // [b][o][p] fp32
__device__ float g_bias[NPOS * NPOS];                          // biasT[g][h]*log2e
__device__ __align__(16) __nv_bfloat16 g_wq_hi[3 * DIMC * KDIM];
__device__ __align__(16) __nv_bfloat16 g_wq_lo[3 * DIMC * KDIM];
__device__ __align__(16) __nv_bfloat16 g_wp_hi[DIMC * KDIM];
__device__ __align__(16) __nv_bfloat16 g_wp_lo[DIMC * KDIM];
__device__ __align__(16) __nv_bfloat16 g_xt_hi[NB * NPOS * KDIM];  // Xt[h][c]
__device__ __align__(16) __nv_bfloat16 g_xt_lo[NB * NPOS * KDIM];
__device__ __align__(16) __nv_bfloat16 g_ot_hi[NB * NPOS * KDIM];  // Ot[h][d]
__device__ __align__(16) __nv_bfloat16 g_ot_lo[NB * NPOS * KDIM];

// ---------------- helpers ----------------
__device__ __forceinline__ uint32_t smem_u32(const void* p) {
    uint32_t a;
    asm("{ .reg .u64 t; cvta.to.shared.u64 t, %1; cvt.u32.u64 %0, t; }" : "=r"(a) : "l"(p));
    return a;
}
#define SWZ128(off) ((off) ^ (((off) >> 3) & 0x70))

__device__ __forceinline__ void ldsm_x4(uint32_t* r, uint32_t addr) {
    asm volatile("ldmatrix.sync.aligned.m8n8.x4.shared.b16 {%0,%1,%2,%3}, [%4];"
                 : "=r"(r[0]), "=r"(r[1]), "=r"(r[2]), "=r"(r[3]) : "r"(addr));
}
__device__ __forceinline__ void mma_bf16(float* d, const uint32_t* a, const uint32_t* b) {
    asm volatile(
        "mma.sync.aligned.m16n8k16.row.col.f32.bf16.bf16.f32 "
        "{%0,%1,%2,%3}, {%4,%5,%6,%7}, {%8,%9}, {%0,%1,%2,%3};"
        : "+f"(d[0]), "+f"(d[1]), "+f"(d[2]), "+f"(d[3])
        : "r"(a[0]), "r"(a[1]), "r"(a[2]), "r"(a[3]), "r"(b[0]), "r"(b[1]));
}

// ---------------- prep: split weights, bias table, transpose+split x --------
__global__ __launch_bounds__(256) void prep(const float* __restrict__ x,
                                            const float* __restrict__ qkv_w,
                                            const float* __restrict__ proj_w,
                                            const float* __restrict__ rpb) {
    const int blk = blockIdx.x, t = threadIdx.x;
    const int NW1 = (3 * DIMC * KDIM) / 256;        // 3072
    const int NW2 = NW1 + (DIMC * KDIM) / 256;      // +1024
    const int NW3 = NW2 + (NPOS * NPOS) / 256;      // +256

    if (blk < NW1) {
        int i = blk * 256 + t;
        float w = qkv_w[i];
        __nv_bfloat16 hi = __float2bfloat16(w);
        g_wq_hi[i] = hi;
        g_wq_lo[i] = __float2bfloat16(w - __bfloat162float(hi));
    } else if (blk < NW2) {
        int i = (blk - NW1) * 256 + t;
        float w = proj_w[i];
        __nv_bfloat16 hi = __float2bfloat16(w);
        g_wp_hi[i] = hi;
        g_wp_lo[i] = __float2bfloat16(w - __bfloat162float(hi));
    } else if (blk < NW3) {
        int i = (blk - NW2) * 256 + t;
        int g = i >> 8, h = i & 255;
        int v = ((h >> 4) - (g >> 4)) + ((h & 15) - (g & 15));
        g_bias[i] = rpb[(v + NTAB) % NTAB] * LOG2E;
    } else {
        // transpose x[b][c][h] -> Xt[b][h][c] (+ hi/lo split)
        int q = blk - NW3;                 // 0..255
        int b = q >> 7;
        int r = q & 127;
        int c0 = (r >> 3) * 32;            // 16 c-tiles
        int h0 = (r & 7) * 32;             // 8 h-tiles
        __shared__ float tile[32][33];
        int tx = t & 31, ty = t >> 5;      // 8 rows of loaders
#pragma unroll
        for (int i = 0; i < 4; i++)
            tile[ty + 8 * i][tx] = (x + (long)b * DIMC * NPOS)
                                   [(long)(c0 + ty + 8 * i) * NPOS + h0 + tx];
        __syncthreads();
#pragma unroll
        for (int i = 0; i < 4; i++) {
            int h = h0 + ty + 8 * i, c = c0 + tx;
            float v = tile[tx][ty + 8 * i];
            __nv_bfloat16 hi = __float2bfloat16(v);
            long o = (long)b * NPOS * KDIM + (long)h * KDIM + c;
            g_xt_hi[o] = hi;
            g_xt_lo[o] = __float2bfloat16(v - __bfloat162float(hi));
        }
    }
}

// ---------------- mma.sync GEMM: C[m][n] = sum_k A[m][k]*B[n][k] + bias[m] --
// A = weights (hi/lo, K-major), B = per-batch activations^T (hi/lo, K-major).
// 64x64 CTA tile, 128 threads = 4 warps (2x2), 32x32 warp tile.
// K in 8 chunks of 64 staged in SW128-swizzled smem; ldmatrix + HMMA.
// 3-term fp32 emulation: Ahi*Bhi + Ahi*Blo + Alo*Bhi.
#define SA_HI 0
#define SA_LO 8192
#define SB_HI 16384
#define SB_LO 24576

__global__ __launch_bounds__(128) void mma_gemm(
        const __nv_bfloat16* __restrict__ Ahi, const __nv_bfloat16* __restrict__ Alo,
        const __nv_bfloat16* __restrict__ Bhi, const __nv_bfloat16* __restrict__ Blo,
        long sB, const float* __restrict__ bias, float* __restrict__ C, long sC) {
    __shared__ __align__(1024) char smem[32768];
    const uint32_t sb = smem_u32(smem);
    const int t = threadIdx.x;
    const int lane = t & 31, wid = t >> 5;
    const int wm = wid & 1, wn = wid >> 1;       // 2 (M) x 2 (N) warps
    const int n0 = blockIdx.x * 64;
    const int m0 = blockIdx.y * 64;
    const int b  = blockIdx.z;

    const __nv_bfloat16* Ah = Ahi + (long)m0 * KDIM;
    const __nv_bfloat16* Al = Alo + (long)m0 * KDIM;
    const __nv_bfloat16* Bh = Bhi + (long)b * sB + (long)n0 * KDIM;
    const __nv_bfloat16* Bl = Blo + (long)b * sB + (long)n0 * KDIM;

    float acc[2][4][4];
#pragma unroll
    for (int i = 0; i < 2; i++)
#pragma unroll
        for (int j = 0; j < 4; j++)
#pragma unroll
            for (int r = 0; r < 4; r++) acc[i][j][r] = 0.f;

    // ldmatrix per-lane row/col (within 64-row, 128B-row tile)
    const int a_row  = wm * 32 + (lane & 15);
    const int a_colb = (lane >> 4) << 4;                       // 0 / 16
    const int b_row  = wn * 32 + (lane & 7) + ((lane >> 4) << 3);
    const int b_colb = ((lane >> 3) & 1) << 4;

    for (int ch = 0; ch < NCHUNK; ch++) {
        const long kb16 = (long)ch * KC;     // bf16 offset into K
        // stage 4 tiles (A hi/lo, B hi/lo): 64 rows x 128B each
#pragma unroll
        for (int i = 0; i < 4; i++) {
            int id = t + i * 128;            // 0..511
            int row = id >> 3, jc = id & 7;
            uint32_t dst = SWZ128((uint32_t)(row * 128 + jc * 16));
            const long go = (long)row * KDIM + kb16 + jc * 8;
            *(uint4*)(smem + SA_HI + dst) = *(const uint4*)(Ah + go);
            *(uint4*)(smem + SA_LO + dst) = *(const uint4*)(Al + go);
            *(uint4*)(smem + SB_HI + dst) = *(const uint4*)(Bh + go);
            *(uint4*)(smem + SB_LO + dst) = *(const uint4*)(Bl + go);
        }
        __syncthreads();

#pragma unroll
        for (int ks = 0; ks < 4; ks++) {
            const int kb = ks * 32;          // byte offset of k16 group
            uint32_t ah[2][4], al[2][4], bh[2][4], bl[2][4];
#pragma unroll
            for (int mi = 0; mi < 2; mi++) {
                uint32_t off = SWZ128((uint32_t)((a_row + mi * 16) * 128 + kb + a_colb));
                ldsm_x4(ah[mi], sb + SA_HI + off);
                ldsm_x4(al[mi], sb + SA_LO + off);
            }
#pragma unroll
            for (int nf = 0; nf < 2; nf++) {
                uint32_t off = SWZ128((uint32_t)((b_row + nf * 16) * 128 + kb + b_colb));
                ldsm_x4(bh[nf], sb + SB_HI + off);
                ldsm_x4(bl[nf], sb + SB_LO + off);
            }
#pragma unroll
            for (int mi = 0; mi < 2; mi++)
#pragma unroll
                for (int nj = 0; nj < 4; nj++) {
                    const uint32_t* bhp = &bh[nj >> 1][(nj & 1) * 2];
                    const uint32_t* blp = &bl[nj >> 1][(nj & 1) * 2];
                    mma_bf16(acc[mi][nj], ah[mi], bhp);
                    mma_bf16(acc[mi][nj], ah[mi], blp);
                    mma_bf16(acc[mi][nj], al[mi], bhp);
                }
        }
        __syncthreads();
    }

    // epilogue: d-frag rows = group, group+8; cols = (lane&3)*2 within n8
    const int g = lane >> 2, tg = lane & 3;
#pragma unroll
    for (int mi = 0; mi < 2; mi++) {
        int mrow = m0 + wm * 32 + mi * 16 + g;
        float b0v = bias[mrow], b1v = bias[mrow + 8];
        float* Crow0 = C + (long)b * sC + (long)mrow * NPOS + n0 + wn * 32;
        float* Crow1 = Crow0 + 8 * NPOS;
#pragma unroll
        for (int nj = 0; nj < 4; nj++) {
            int c = nj * 8 + tg * 2;
            Crow0[c]     = acc[mi][nj][0] + b0v;
            Crow0[c + 1] = acc[mi][nj][1] + b0v;
            Crow1[c]     = acc[mi][nj][2] + b1v;
            Crow1[c + 1] = acc[mi][nj][3] + b1v;
        }
    }
}

// ---------------- per-channel attention (outputs transposed + hi/lo split) --
__global__ __launch_bounds__(256) void chan_attn() {
    const int b  = blockIdx.y;
    const int d0 = blockIdx.x * DBLK;
    const int h  = threadIdx.x;

    const float* base = g_qkv + (long)b * 3 * DIMC * NPOS;
    __shared__ float2 skv[DBLK][NPOS];

    float a[DBLK], num[DBLK], den[DBLK];
#pragma unroll
    for (int d = 0; d < DBLK; d++) {
        float kk = base[(long)(DIMC     + d0 + d) * NPOS + h];
        float vv = base[(long)(2 * DIMC + d0 + d) * NPOS + h];
        skv[d][h] = make_float2(kk, vv);
        a[d]   = base[(long)(d0 + d) * NPOS + h] * (SCALE * LOG2E);
        num[d] = 0.f;
        den[d] = 0.f;
    }
    __syncthreads();

    const float* bp = g_bias + h;
#pragma unroll 4
    for (int g = 0; g < NPOS; g++) {
        float bb = __ldg(bp + g * NPOS);
#pragma unroll
        for (int d = 0; d < DBLK; d++) {
            float2 kv = skv[d][g];
            float e = exp2f(fmaf(a[d], kv.x, bb));
            num[d] = fmaf(e, kv.y, num[d]);
            den[d] += e;
        }
    }

    __nv_bfloat16 oh[DBLK], ol[DBLK];
#pragma unroll
    for (int d = 0; d < DBLK; d++) {
        float o = num[d] / den[d];
        oh[d] = __float2bfloat16(o);
        ol[d] = __float2bfloat16(o - __bfloat162float(oh[d]));
    }
    long off = ((long)b * NPOS + h) * KDIM + d0;
    *(uint4*)(g_ot_hi + off) = *(const uint4*)oh;
    *(uint4*)(g_ot_lo + off) = *(const uint4*)ol;
}

// ---------------------------------------------------------------------------
extern "C" void kernel_launch(void* const* d_in, const int* in_sizes, int n_in,
                              void* d_out, int out_size) {
    const float* x      = (const float*)d_in[0];
    const float* qkv_w  = (const float*)d_in[1];
    const float* qkv_b  = (const float*)d_in[2];
    const float* proj_w = (const float*)d_in[3];
    const float* proj_b = (const float*)d_in[4];
    const float* rpb    = (const float*)d_in[5];
    float* out = (float*)d_out;

    float* qkv_ptr;
    __nv_bfloat16 *wqh, *wql, *wph, *wpl, *xth, *xtl, *oth, *otl;
    cudaGetSymbolAddress((void**)&qkv_ptr, g_qkv);
    cudaGetSymbolAddress((void**)&wqh, g_wq_hi);
    cudaGetSymbolAddress((void**)&wql, g_wq_lo);
    cudaGetSymbolAddress((void**)&wph, g_wp_hi);
    cudaGetSymbolAddress((void**)&wpl, g_wp_lo);
    cudaGetSymbolAddress((void**)&xth, g_xt_hi);
    cudaGetSymbolAddress((void**)&xtl, g_xt_lo);
    cudaGetSymbolAddress((void**)&oth, g_ot_hi);
    cudaGetSymbolAddress((void**)&otl, g_ot_lo);

    // 1) prep: weight split + bias table + x transpose/split
    prep<<<3072 + 1024 + 256 + 256, 256>>>(x, qkv_w, proj_w, rpb);

    // 2) QKV = qkv_w * Xt^T (+b) -> g_qkv fp32 [o][p]   (192 CTAs)
    {
        dim3 grid(NPOS / 64, (3 * DIMC) / 64, NB);   // (4, 24, 2)
        mma_gemm<<<grid, 128>>>(wqh, wql, xth, xtl,
                                (long)NPOS * KDIM, qkv_b,
                                qkv_ptr, (long)3 * DIMC * NPOS);
    }

    // 3) per-channel attention -> Ot hi/lo (128 CTAs)
    {
        dim3 grid(DIMC / DBLK, NB);
        chan_attn<<<grid, 256>>>();
    }

    // 4) out = proj_w * Ot^T (+b)   (64 CTAs)
    {
        dim3 grid(NPOS / 64, DIMC / 64, NB);          // (4, 8, 2)
        mma_gemm<<<grid, 128>>>(wph, wpl, oth, otl,
                                (long)NPOS * KDIM, proj_b,
                                out, (long)DIMC * NPOS);
    }
}

// round 9
// speedup vs baseline: 1.6047x; 1.0932x over previous
#include <cuda_runtime.h>
#include <cuda_bf16.h>
#include <cstdint>

#define DIMC  512
#define NPOS  256
#define NB    2
#define NTAB  961
#define KDIM  512
#define KC    64                 // bf16 k per chunk = 128 bytes = SW128 row
#define NCHUNK (KDIM / KC)
#define LOG2E 1.4426950408889634f
#define SCALE 0.044194173824159216f   // 512^-0.5
#define DBLK  8

// ---------------- scratch (device globals; no allocs) ----------------
__device__ float g_qkv [NB * 3 * DIMC * NPOS];                 // [b][o][p] fp32
__device__ float g_bias[NPOS * NPOS];                          // biasT[g][h]*log2e
__device__ __align__(16) __nv_bfloat16 g_wq_hi[3 * DIMC * KDIM];
__device__ __align__(16) __nv_bfloat16 g_wq_lo[3 * DIMC * KDIM];
__device__ __align__(16) __nv_bfloat16 g_wp_hi[DIMC * KDIM];
__device__ __align__(16) __nv_bfloat16 g_wp_lo[DIMC * KDIM];
__device__ __align__(16) __nv_bfloat16 g_xt_hi[NB * NPOS * KDIM];  // Xt[h][c]
__device__ __align__(16) __nv_bfloat16 g_xt_lo[NB * NPOS * KDIM];
__device__ __align__(16) __nv_bfloat16 g_ot_hi[NB * NPOS * KDIM];  // Ot[h][d]
__device__ __align__(16) __nv_bfloat16 g_ot_lo[NB * NPOS * KDIM];

// ---------------- helpers ----------------
__device__ __forceinline__ uint32_t smem_u32(const void* p) {
    uint32_t a;
    asm("{ .reg .u64 t; cvta.to.shared.u64 t, %1; cvt.u32.u64 %0, t; }" : "=r"(a) : "l"(p));
    return a;
}
#define SWZ128(off) ((off) ^ (((off) >> 3) & 0x70))

__device__ __forceinline__ void ldsm_x4(uint32_t* r, uint32_t addr) {
    asm volatile("ldmatrix.sync.aligned.m8n8.x4.shared.b16 {%0,%1,%2,%3}, [%4];"
                 : "=r"(r[0]), "=r"(r[1]), "=r"(r[2]), "=r"(r[3]) : "r"(addr));
}
__device__ __forceinline__ void mma_bf16(float* d, const uint32_t* a, const uint32_t* b) {
    asm volatile(
        "mma.sync.aligned.m16n8k16.row.col.f32.bf16.bf16.f32 "
        "{%0,%1,%2,%3}, {%4,%5,%6,%7}, {%8,%9}, {%0,%1,%2,%3};"
        : "+f"(d[0]), "+f"(d[1]), "+f"(d[2]), "+f"(d[3])
        : "r"(a[0]), "r"(a[1]), "r"(a[2]), "r"(a[3]), "r"(b[0]), "r"(b[1]));
}

// ---------------- prep: split weights (x4 vec), bias table, transpose x -----
__global__ __launch_bounds__(256) void prep(const float* __restrict__ x,
                                            const float* __restrict__ qkv_w,
                                            const float* __restrict__ proj_w,
                                            const float* __restrict__ rpb) {
    const int blk = blockIdx.x, t = threadIdx.x;
    const int NW1 = (3 * DIMC * KDIM) / 1024;       // 768  (x4 vectorized)
    const int NW2 = NW1 + (DIMC * KDIM) / 1024;     // +256
    const int NW3 = NW2 + (NPOS * NPOS) / 256;      // +256

    if (blk < NW2) {
        const bool isQ = blk < NW1;
        const float* W = isQ ? qkv_w : proj_w;
        __nv_bfloat16* Hi = isQ ? g_wq_hi : g_wp_hi;
        __nv_bfloat16* Lo = isQ ? g_wq_lo : g_wp_lo;
        long i = ((long)(isQ ? blk : blk - NW1) * 256 + t) * 4;
        float4 w = *(const float4*)(W + i);
        __nv_bfloat16 h0 = __float2bfloat16(w.x), h1 = __float2bfloat16(w.y);
        __nv_bfloat16 h2 = __float2bfloat16(w.z), h3 = __float2bfloat16(w.w);
        __nv_bfloat16 hv[4] = {h0, h1, h2, h3};
        __nv_bfloat16 lv[4] = {
            __float2bfloat16(w.x - __bfloat162float(h0)),
            __float2bfloat16(w.y - __bfloat162float(h1)),
            __float2bfloat16(w.z - __bfloat162float(h2)),
            __float2bfloat16(w.w - __bfloat162float(h3))};
        *(uint2*)(Hi + i) = *(const uint2*)hv;
        *(uint2*)(Lo + i) = *(const uint2*)lv;
    } else if (blk < NW3) {
        int i = (blk - NW2) * 256 + t;
        int g = i >> 8, h = i & 255;
        int v = ((h >> 4) - (g >> 4)) + ((h & 15) - (g & 15));
        g_bias[i] = rpb[(v + NTAB) % NTAB] * LOG2E;
    } else {
        // transpose x[b][c][h] -> Xt[b][h][c] (+ hi/lo split)
        int q = blk - NW3;                 // 0..255
        int b = q >> 7;
        int r = q & 127;
        int c0 = (r >> 3) * 32;            // 16 c-tiles
        int h0 = (r & 7) * 32;             // 8 h-tiles
        __shared__ float tile[32][33];
        int tx = t & 31, ty = t >> 5;
#pragma unroll
        for (int i = 0; i < 4; i++)
            tile[ty + 8 * i][tx] = (x + (long)b * DIMC * NPOS)
                                   [(long)(c0 + ty + 8 * i) * NPOS + h0 + tx];
        __syncthreads();
#pragma unroll
        for (int i = 0; i < 4; i++) {
            int h = h0 + ty + 8 * i, c = c0 + tx;
            float v = tile[tx][ty + 8 * i];
            __nv_bfloat16 hi = __float2bfloat16(v);
            long o = (long)b * NPOS * KDIM + (long)h * KDIM + c;
            g_xt_hi[o] = hi;
            g_xt_lo[o] = __float2bfloat16(v - __bfloat162float(hi));
        }
    }
}

// ---------------- mma.sync GEMM: C[m][n] = sum_k A[m][k]*B[n][k] + bias[m] --
// 64x64 CTA tile, 256 threads = 8 warps (2 M x 4 N), 32x16 warp tile.
// K in 8 chunks of 64; register-prefetch double buffering on global loads.
// 3-term fp32 emulation: Ahi*Bhi + Ahi*Blo + Alo*Bhi.
#define SA_HI 0
#define SA_LO 8192
#define SB_HI 16384
#define SB_LO 24576

__global__ __launch_bounds__(256) void mma_gemm(
        const __nv_bfloat16* __restrict__ Ahi, const __nv_bfloat16* __restrict__ Alo,
        const __nv_bfloat16* __restrict__ Bhi, const __nv_bfloat16* __restrict__ Blo,
        long sB, const float* __restrict__ bias, float* __restrict__ C, long sC) {
    __shared__ __align__(1024) char smem[32768];
    const uint32_t sb = smem_u32(smem);
    const int t = threadIdx.x;
    const int lane = t & 31, wid = t >> 5;
    const int wm = wid & 1, wn = wid >> 1;       // 2 (M) x 4 (N)
    const int n0 = blockIdx.x * 64;
    const int m0 = blockIdx.y * 64;
    const int b  = blockIdx.z;

    const __nv_bfloat16* Ah = Ahi + (long)m0 * KDIM;
    const __nv_bfloat16* Al = Alo + (long)m0 * KDIM;
    const __nv_bfloat16* Bh = Bhi + (long)b * sB + (long)n0 * KDIM;
    const __nv_bfloat16* Bl = Blo + (long)b * sB + (long)n0 * KDIM;

    float acc[2][2][4];
#pragma unroll
    for (int i = 0; i < 2; i++)
#pragma unroll
        for (int j = 0; j < 2; j++)
#pragma unroll
            for (int r = 0; r < 4; r++) acc[i][j][r] = 0.f;

    // per-thread staging slots: 2 x 16B per tile
    int rowi[2], jci[2];
    uint32_t dsti[2];
#pragma unroll
    for (int i = 0; i < 2; i++) {
        int id = t + i * 256;                 // 0..511
        rowi[i] = id >> 3; jci[i] = id & 7;
        dsti[i] = SWZ128((uint32_t)(rowi[i] * 128 + jci[i] * 16));
    }

    // ldmatrix per-lane addressing
    const int a_row  = wm * 32 + (lane & 15);
    const int a_colb = (lane >> 4) << 4;
    const int b_row  = wn * 16 + (lane & 7) + ((lane >> 4) << 3);
    const int b_colb = ((lane >> 3) & 1) << 4;

    uint4 pah[2], pal[2], pbh[2], pbl[2];
    // prologue: fetch chunk 0
#pragma unroll
    for (int i = 0; i < 2; i++) {
        long go = (long)rowi[i] * KDIM + jci[i] * 8;
        pah[i] = *(const uint4*)(Ah + go);
        pal[i] = *(const uint4*)(Al + go);
        pbh[i] = *(const uint4*)(Bh + go);
        pbl[i] = *(const uint4*)(Bl + go);
    }

    for (int ch = 0; ch < NCHUNK; ch++) {
        // store staged chunk to smem
#pragma unroll
        for (int i = 0; i < 2; i++) {
            *(uint4*)(smem + SA_HI + dsti[i]) = pah[i];
            *(uint4*)(smem + SA_LO + dsti[i]) = pal[i];
            *(uint4*)(smem + SB_HI + dsti[i]) = pbh[i];
            *(uint4*)(smem + SB_LO + dsti[i]) = pbl[i];
        }
        __syncthreads();

        // prefetch next chunk while computing
        if (ch + 1 < NCHUNK) {
            const long kb16 = (long)(ch + 1) * KC;
#pragma unroll
            for (int i = 0; i < 2; i++) {
                long go = (long)rowi[i] * KDIM + kb16 + jci[i] * 8;
                pah[i] = *(const uint4*)(Ah + go);
                pal[i] = *(const uint4*)(Al + go);
                pbh[i] = *(const uint4*)(Bh + go);
                pbl[i] = *(const uint4*)(Bl + go);
            }
        }

#pragma unroll
        for (int ks = 0; ks < 4; ks++) {
            const int kb = ks * 32;
            uint32_t ah[2][4], al[2][4], bh[4], bl[4];
#pragma unroll
            for (int mi = 0; mi < 2; mi++) {
                uint32_t off = SWZ128((uint32_t)((a_row + mi * 16) * 128 + kb + a_colb));
                ldsm_x4(ah[mi], sb + SA_HI + off);
                ldsm_x4(al[mi], sb + SA_LO + off);
            }
            {
                uint32_t off = SWZ128((uint32_t)(b_row * 128 + kb + b_colb));
                ldsm_x4(bh, sb + SB_HI + off);
                ldsm_x4(bl, sb + SB_LO + off);
            }
#pragma unroll
            for (int mi = 0; mi < 2; mi++)
#pragma unroll
                for (int nj = 0; nj < 2; nj++) {
                    mma_bf16(acc[mi][nj], ah[mi], &bh[nj * 2]);
                    mma_bf16(acc[mi][nj], ah[mi], &bl[nj * 2]);
                    mma_bf16(acc[mi][nj], al[mi], &bh[nj * 2]);
                }
        }
        __syncthreads();
    }

    // epilogue
    const int g = lane >> 2, tg = lane & 3;
#pragma unroll
    for (int mi = 0; mi < 2; mi++) {
        int mrow = m0 + wm * 32 + mi * 16 + g;
        float b0v = bias[mrow], b1v = bias[mrow + 8];
        float* Crow0 = C + (long)b * sC + (long)mrow * NPOS + n0 + wn * 16;
        float* Crow1 = Crow0 + 8 * NPOS;
#pragma unroll
        for (int nj = 0; nj < 2; nj++) {
            int c = nj * 8 + tg * 2;
            Crow0[c]     = acc[mi][nj][0] + b0v;
            Crow0[c + 1] = acc[mi][nj][1] + b0v;
            Crow1[c]     = acc[mi][nj][2] + b1v;
            Crow1[c + 1] = acc[mi][nj][3] + b1v;
        }
    }
}

// ---------------- per-channel attention (outputs transposed + hi/lo split) --
__global__ __launch_bounds__(256) void chan_attn() {
    const int b  = blockIdx.y;
    const int d0 = blockIdx.x * DBLK;
    const int h  = threadIdx.x;

    const float* base = g_qkv + (long)b * 3 * DIMC * NPOS;
    __shared__ float2 skv[DBLK][NPOS];

    float a[DBLK], num[DBLK], den[DBLK];
#pragma unroll
    for (int d = 0; d < DBLK; d++) {
        float kk = base[(long)(DIMC     + d0 + d) * NPOS + h];
        float vv = base[(long)(2 * DIMC + d0 + d) * NPOS + h];
        skv[d][h] = make_float2(kk, vv);
        a[d]   = base[(long)(d0 + d) * NPOS + h] * (SCALE * LOG2E);
        num[d] = 0.f;
        den[d] = 0.f;
    }
    __syncthreads();

    const float* bp = g_bias + h;
#pragma unroll 4
    for (int g = 0; g < NPOS; g++) {
        float bb = __ldg(bp + g * NPOS);
#pragma unroll
        for (int d = 0; d < DBLK; d++) {
            float2 kv = skv[d][g];
            float e = exp2f(fmaf(a[d], kv.x, bb));
            num[d] = fmaf(e, kv.y, num[d]);
            den[d] += e;
        }
    }

    __nv_bfloat16 oh[DBLK], ol[DBLK];
#pragma unroll
    for (int d = 0; d < DBLK; d++) {
        float o = num[d] / den[d];
        oh[d] = __float2bfloat16(o);
        ol[d] = __float2bfloat16(o - __bfloat162float(oh[d]));
    }
    long off = ((long)b * NPOS + h) * KDIM + d0;
    *(uint4*)(g_ot_hi + off) = *(const uint4*)oh;
    *(uint4*)(g_ot_lo + off) = *(const uint4*)ol;
}

// ---------------------------------------------------------------------------
extern "C" void kernel_launch(void* const* d_in, const int* in_sizes, int n_in,
                              void* d_out, int out_size) {
    const float* x      = (const float*)d_in[0];
    const float* qkv_w  = (const float*)d_in[1];
    const float* qkv_b  = (const float*)d_in[2];
    const float* proj_w = (const float*)d_in[3];
    const float* proj_b = (const float*)d_in[4];
    const float* rpb    = (const float*)d_in[5];
    float* out = (float*)d_out;

    float* qkv_ptr;
    __nv_bfloat16 *wqh, *wql, *wph, *wpl, *xth, *xtl, *oth, *otl;
    cudaGetSymbolAddress((void**)&qkv_ptr, g_qkv);
    cudaGetSymbolAddress((void**)&wqh, g_wq_hi);
    cudaGetSymbolAddress((void**)&wql, g_wq_lo);
    cudaGetSymbolAddress((void**)&wph, g_wp_hi);
    cudaGetSymbolAddress((void**)&wpl, g_wp_lo);
    cudaGetSymbolAddress((void**)&xth, g_xt_hi);
    cudaGetSymbolAddress((void**)&xtl, g_xt_lo);
    cudaGetSymbolAddress((void**)&oth, g_ot_hi);
    cudaGetSymbolAddress((void**)&otl, g_ot_lo);

    // 1) prep: weight split + bias table + x transpose/split
    prep<<<768 + 256 + 256 + 256, 256>>>(x, qkv_w, proj_w, rpb);

    // 2) QKV = qkv_w * Xt^T (+b) -> g_qkv fp32 [o][p]   (192 CTAs)
    {
        dim3 grid(NPOS / 64, (3 * DIMC) / 64, NB);   // (4, 24, 2)
        mma_gemm<<<grid, 256>>>(wqh, wql, xth, xtl,
                                (long)NPOS * KDIM, qkv_b,
                                qkv_ptr, (long)3 * DIMC * NPOS);
    }

    // 3) per-channel attention -> Ot hi/lo (128 CTAs)
    {
        dim3 grid(DIMC / DBLK, NB);
        chan_attn<<<grid, 256>>>();
    }

    // 4) out = proj_w * Ot^T (+b)   (64 CTAs)
    {
        dim3 grid(NPOS / 64, DIMC / 64, NB);          // (4, 8, 2)
        mma_gemm<<<grid, 256>>>(wph, wpl, oth, otl,
                                (long)NPOS * KDIM, proj_b,
                                out, (long)DIMC * NPOS);
    }
}